// round 16
// baseline (speedup 1.0000x reference)
#include <cuda_runtime.h>
#include <cuda_fp16.h>

#define Nn 40000
#define NPAD 40064
#define Mm 10000
#define NNZv 400000
#define FT 128
#define HID 256
#define NCLS 10
#define NG 128
#define BN_EPS 1e-5f
#define NTOT (Mm + Nn)
#define NCHUNK ((NTOT + 1023) / 1024)

// ---------------- scratch ----------------
__device__ unsigned g_A[(size_t)NPAD * 128];
__device__ unsigned g_C[(size_t)NPAD * 128];
__device__ unsigned g_hh[(size_t)Nn * 128];
__device__ unsigned g_P0h[(size_t)NPAD * 128];
__device__ unsigned g_W[114688];
__device__ unsigned g_q[(size_t)Nn * 8];
__device__ unsigned g_qe[(size_t)Mm * 8];
__device__ unsigned g_qr[(size_t)Nn * 8];
__device__ __half g_Xh[(size_t)Nn * FT];
__device__ __half g_Eh[(size_t)Mm * HID];
__device__ float g_dinv[Nn];
__device__ float g_stats[4 * 2 * HID];   // one (sum|sumsq) pair per GEMM
__device__ float g_segsum[NG * NCLS];
__device__ float g_segcnt[NG];
__device__ int g_ecnt[Mm];
__device__ int g_estart[Mm + 1];
__device__ int g_ecur[Mm];
__device__ int g_elist[NNZv];
__device__ int g_ncnt[Nn];
__device__ int g_nstart[Nn + 1];
__device__ int g_ncur[Nn];
__device__ int g_nlist[NNZv];
__device__ int g_blksum[NCHUNK];

#define OFF_W10 0
#define OFF_W20 16384
#define OFF_W11 49152
#define OFF_W21 81920

// ---------------- init ----------------
__global__ void k_init(int* ecnt, int* ncnt, float* stats, float* ssum, float* scnt) {
    int i = blockIdx.x * blockDim.x + threadIdx.x;
    int stride = gridDim.x * blockDim.x;
    for (int j = i; j < Mm; j += stride) ecnt[j] = 0;
    for (int j = i; j < Nn; j += stride) ncnt[j] = 0;
    if (i < 4 * 2 * HID) stats[i] = 0.f;
    if (i < NG * NCLS) ssum[i] = 0.f;
    if (i < NG) scnt[i] = 0.f;
}

__global__ void k_wsplit_all(const float* __restrict__ W10, const float* __restrict__ W20,
                             const float* __restrict__ W11, const float* __restrict__ W21,
                             unsigned* __restrict__ o) {
    int idx = blockIdx.x * blockDim.x + threadIdx.x;
    if (idx >= 114688) return;
    const float* W;
    int li;
    if (idx < 16384) { W = W10; li = idx; }
    else if (idx < 49152) { W = W20; li = idx - 16384; }
    else if (idx < 81920) { W = W11; li = idx - 49152; }
    else { W = W21; li = idx - 81920; }
    int kp = li / HID, c = li % HID;
    __half2 h = __floats2half2_rn(W[(size_t)(2 * kp) * HID + c],
                                  W[(size_t)(2 * kp + 1) * HID + c]);
    o[idx] = *(unsigned*)&h;
}

// ---------------- CSR build ----------------
__global__ void k_hist(const int* __restrict__ nidx, const int* __restrict__ eidx,
                       int* __restrict__ ecnt, int* __restrict__ ncnt) {
    int i = blockIdx.x * blockDim.x + threadIdx.x;
    if (i < NNZv) {
        atomicAdd(&ecnt[eidx[i]], 1);
        atomicAdd(&ncnt[nidx[i]], 1);
    }
}

__global__ void k_scan_blk(const int* __restrict__ ecnt, const int* __restrict__ ncnt,
                           int* __restrict__ estart, int* __restrict__ nstart,
                           int* __restrict__ blksum) {
    __shared__ int wsum[32];
    int t = threadIdx.x, w = t >> 5, l = t & 31;
    int gi = blockIdx.x * 1024 + t;
    int v = 0;
    if (gi < Mm) v = ecnt[gi];
    else if (gi < NTOT) v = ncnt[gi - Mm];
    int x = v;
#pragma unroll
    for (int off = 1; off < 32; off <<= 1) {
        int y = __shfl_up_sync(0xffffffffu, x, off);
        if (l >= off) x += y;
    }
    if (l == 31) wsum[w] = x;
    __syncthreads();
    if (w == 0) {
        int s = wsum[l];
#pragma unroll
        for (int off = 1; off < 32; off <<= 1) {
            int y = __shfl_up_sync(0xffffffffu, s, off);
            if (l >= off) s += y;
        }
        wsum[l] = s;
    }
    __syncthreads();
    int excl = x - v + (w ? wsum[w - 1] : 0);
    if (gi < Mm) estart[gi] = excl;
    else if (gi < NTOT) nstart[gi - Mm] = excl;
    if (t == 1023) blksum[blockIdx.x] = excl + v;
}

__global__ void k_scan_add(int* __restrict__ estart, int* __restrict__ nstart,
                           int* __restrict__ ecur, int* __restrict__ ncur,
                           const int* __restrict__ blksum) {
    __shared__ int offs;
    int t = threadIdx.x;
    if (t == 0) {
        int o = 0;
        for (int c = 0; c < (int)blockIdx.x; c++) o += blksum[c];
        offs = o;
    }
    __syncthreads();
    int gi = blockIdx.x * 1024 + t;
    if (gi < Mm) {
        int v = estart[gi] + offs;
        estart[gi] = v;
        ecur[gi] = v;
    } else if (gi < NTOT) {
        int v = nstart[gi - Mm] + offs - NNZv;
        nstart[gi - Mm] = v;
        ncur[gi - Mm] = v;
    }
    if (gi == 0) {
        estart[Mm] = NNZv;
        nstart[Nn] = NNZv;
    }
}

__global__ void k_fill(const int* __restrict__ nidx, const int* __restrict__ eidx,
                       int* __restrict__ ecur, int* __restrict__ elist,
                       int* __restrict__ ncur, int* __restrict__ nlist) {
    int i = blockIdx.x * blockDim.x + threadIdx.x;
    if (i < NNZv) {
        int e = eidx[i], n = nidx[i];
        elist[atomicAdd(&ecur[e], 1)] = n;
        nlist[atomicAdd(&ncur[n], 1)] = e;
    }
}

// ---------------- converts ----------------
__device__ __forceinline__ uint4 pack8h(const float* f) {
    uint4 u;
    __half2 h0 = __float22half2_rn(make_float2(f[0], f[1]));
    __half2 h1 = __float22half2_rn(make_float2(f[2], f[3]));
    __half2 h2 = __float22half2_rn(make_float2(f[4], f[5]));
    __half2 h3 = __float22half2_rn(make_float2(f[6], f[7]));
    u.x = *(unsigned*)&h0; u.y = *(unsigned*)&h1;
    u.z = *(unsigned*)&h2; u.w = *(unsigned*)&h3;
    return u;
}

__global__ void k_cvtX(const float* __restrict__ src, uint4* __restrict__ dst) {
    int i = blockIdx.x * blockDim.x + threadIdx.x;
    if (i >= Nn * FT / 8) return;
    float f[8];
    *(float4*)&f[0] = *(const float4*)(src + (size_t)i * 8);
    *(float4*)&f[4] = *(const float4*)(src + (size_t)i * 8 + 4);
    dst[i] = pack8h(f);
}

// bn params computed inline from stats + gamma/beta
__device__ __forceinline__ void bn_inline(const float* stats, const float* g,
                                          const float* b, int c, float& sc, float& sh) {
    float mean = __ldg(&stats[c]) * (1.f / Nn);
    float var = __ldg(&stats[HID + c]) * (1.f / Nn) - mean * mean;
    sc = __ldg(&g[c]) * rsqrtf(var + BN_EPS);
    sh = __ldg(&b[c]) - mean * sc;
}

// fp16 in -> relu(bn(x)) fp16 out, bn from stats inline
__global__ void k_bnrelu_cvt(const uint4* __restrict__ src, const float* __restrict__ stats,
                             const float* __restrict__ g, const float* __restrict__ b,
                             uint4* __restrict__ dst) {
    int i = blockIdx.x * blockDim.x + threadIdx.x;
    if (i >= Nn * HID / 8) return;
    int c8 = (i & 31) * 8;
    uint4 u = src[i];
    float f[8];
    const __half2* h = (const __half2*)&u;
#pragma unroll
    for (int q = 0; q < 4; q++) {
        float2 v = __half22float2(h[q]);
        f[2 * q] = v.x;
        f[2 * q + 1] = v.y;
    }
#pragma unroll
    for (int j = 0; j < 8; j++) {
        float sc, sh;
        bn_inline(stats, g, b, c8 + j, sc, sh);
        f[j] = fmaxf(f[j] * sc + sh, 0.f);
    }
    dst[i] = pack8h(f);
}

// ---------------- fp16 CSR segment-sum gather ----------------
__device__ __forceinline__ void acc8(float* acc, uint4 v) {
    const __half2* h = (const __half2*)&v;
#pragma unroll
    for (int q = 0; q < 4; q++) {
        float2 f = __half22float2(h[q]);
        acc[2 * q] += f.x;
        acc[2 * q + 1] += f.y;
    }
}

template <int D>
__global__ void k_gath(const uint4* __restrict__ src, const int* __restrict__ start,
                       const int* __restrict__ list, uint4* __restrict__ d0, int rows) {
    int row = (blockIdx.x * blockDim.x + threadIdx.x) >> 5;
    int lane = threadIdx.x & 31;
    if (row >= rows) return;
    int s = __ldg(&start[row]), e = __ldg(&start[row + 1]);
    float acc[8] = {};
    if (D == 256) {
        for (int j0 = s; j0 < e; j0 += 32) {
            int cnt = min(32, e - j0);
            int id = (lane < cnt) ? __ldg(&list[j0 + lane]) : 0;
            int jj = 0;
            for (; jj + 4 <= cnt; jj += 4) {
                int r0 = __shfl_sync(0xffffffffu, id, jj);
                int r1 = __shfl_sync(0xffffffffu, id, jj + 1);
                int r2 = __shfl_sync(0xffffffffu, id, jj + 2);
                int r3 = __shfl_sync(0xffffffffu, id, jj + 3);
                uint4 v0 = __ldg(&src[(size_t)r0 * 32 + lane]);
                uint4 v1 = __ldg(&src[(size_t)r1 * 32 + lane]);
                uint4 v2 = __ldg(&src[(size_t)r2 * 32 + lane]);
                uint4 v3 = __ldg(&src[(size_t)r3 * 32 + lane]);
                acc8(acc, v0); acc8(acc, v1); acc8(acc, v2); acc8(acc, v3);
            }
            for (; jj < cnt; jj++) {
                int r = __shfl_sync(0xffffffffu, id, jj);
                acc8(acc, __ldg(&src[(size_t)r * 32 + lane]));
            }
        }
    } else {
        int oct = lane & 15, par = lane >> 4;
        for (int j0 = s; j0 < e; j0 += 32) {
            int cnt = min(32, e - j0);
            int id = (lane < cnt) ? __ldg(&list[j0 + lane]) : 0;
            int jj = 0;
            for (; jj + 4 <= cnt; jj += 4) {
                int q0 = __shfl_sync(0xffffffffu, id, jj);
                int q1 = __shfl_sync(0xffffffffu, id, jj + 1);
                int q2 = __shfl_sync(0xffffffffu, id, jj + 2);
                int q3 = __shfl_sync(0xffffffffu, id, jj + 3);
                int ra = par ? q1 : q0;
                int rb = par ? q3 : q2;
                uint4 va = __ldg(&src[(size_t)ra * 16 + oct]);
                uint4 vb = __ldg(&src[(size_t)rb * 16 + oct]);
                acc8(acc, va); acc8(acc, vb);
            }
            for (; jj < cnt; jj += 2) {
                int q0 = __shfl_sync(0xffffffffu, id, jj);
                int q1 = __shfl_sync(0xffffffffu, id, min(jj + 1, cnt - 1));
                int idxn = jj + par;
                int r = par ? q1 : q0;
                if (idxn < cnt)
                    acc8(acc, __ldg(&src[(size_t)r * 16 + oct]));
            }
        }
#pragma unroll
        for (int q = 0; q < 8; q++) acc[q] += __shfl_xor_sync(0xffffffffu, acc[q], 16);
        if (par) return;
        lane = oct;
    }
    d0[(size_t)row * (D / 8) + lane] = pack8h(acc);
}

// ---------------- D=16 gathers ----------------
// edge pass (plain)
__global__ void k_gath16(const uint4* __restrict__ src, const int* __restrict__ start,
                         const int* __restrict__ list, uint4* __restrict__ dst, int rows) {
    int row = (blockIdx.x * blockDim.x + threadIdx.x) >> 5;
    int lane = threadIdx.x & 31;
    if (row >= rows) return;
    int s = __ldg(&start[row]), e = __ldg(&start[row + 1]);
    float acc[16] = {};
    for (int j = s + lane; j < e; j += 32) {
        int r = __ldg(&list[j]);
        uint4 a = __ldg(&src[(size_t)r * 2]);
        uint4 b = __ldg(&src[(size_t)r * 2 + 1]);
        acc8(acc, a);
        acc8(acc + 8, b);
    }
#pragma unroll
    for (int off = 16; off > 0; off >>= 1)
#pragma unroll
        for (int q = 0; q < 16; q++) acc[q] += __shfl_xor_sync(0xffffffffu, acc[q], off);
    if (lane == 0) {
        dst[(size_t)row * 2] = pack8h(acc);
        dst[(size_t)row * 2 + 1] = pack8h(acc + 8);
    }
}

// node pass + fused dinv computation (walks nlist anyway)
__global__ void k_gath16_dinv(const uint4* __restrict__ src, const int* __restrict__ nstart,
                              const int* __restrict__ nlist, const int* __restrict__ estart,
                              uint4* __restrict__ dst, float* __restrict__ dinv) {
    int row = (blockIdx.x * blockDim.x + threadIdx.x) >> 5;
    int lane = threadIdx.x & 31;
    if (row >= Nn) return;
    int s = __ldg(&nstart[row]), e = __ldg(&nstart[row + 1]);
    float acc[16] = {};
    float dsum = 0.f;
    for (int j = s + lane; j < e; j += 32) {
        int r = __ldg(&nlist[j]);
        uint4 a = __ldg(&src[(size_t)r * 2]);
        uint4 b = __ldg(&src[(size_t)r * 2 + 1]);
        acc8(acc, a);
        acc8(acc + 8, b);
        dsum += (float)(__ldg(&estart[r + 1]) - __ldg(&estart[r]));
    }
#pragma unroll
    for (int off = 16; off > 0; off >>= 1) {
#pragma unroll
        for (int q = 0; q < 16; q++) acc[q] += __shfl_xor_sync(0xffffffffu, acc[q], off);
        dsum += __shfl_xor_sync(0xffffffffu, dsum, off);
    }
    if (lane == 0) {
        dst[(size_t)row * 2] = pack8h(acc);
        dst[(size_t)row * 2 + 1] = pack8h(acc + 8);
        dinv[row] = (dsum > 0.f) ? 1.f / dsum : 1.f;
    }
}

// ---------------- fp16 tensor-core GEMM ----------------
__device__ __forceinline__ void mma16f(float* c, const unsigned* a, unsigned b0, unsigned b1) {
    asm volatile(
        "mma.sync.aligned.m16n8k16.row.col.f32.f16.f16.f32 "
        "{%0,%1,%2,%3}, {%4,%5,%6,%7}, {%8,%9}, {%0,%1,%2,%3};"
        : "+f"(c[0]), "+f"(c[1]), "+f"(c[2]), "+f"(c[3])
        : "r"(a[0]), "r"(a[1]), "r"(a[2]), "r"(a[3]), "r"(b0), "r"(b1));
}

__global__ __launch_bounds__(256) void k_gemm_tc(
    const unsigned* __restrict__ Ag, const unsigned* __restrict__ Bg,
    const float* __restrict__ bias, unsigned* __restrict__ Ch,
    float* __restrict__ stats, int K, int Nc, int Mrows) {
    __shared__ unsigned As[8][132];
    __shared__ unsigned Bs[8][132];
    __shared__ float shS[128], shQ[128];
    const int t = threadIdx.x;
    const int wid = t >> 5, lane = t & 31;
    const int wm = wid & 3, wn = wid >> 2;
    const int g = lane >> 2, tg = lane & 3;
    const int row0 = blockIdx.y * 128, col0 = blockIdx.x * 128;
    const int Kp = K / 2;
    const int Nc2 = Nc / 2;

    float acc[2][8][4];
#pragma unroll
    for (int i = 0; i < 2; i++)
#pragma unroll
        for (int j = 0; j < 8; j++)
#pragma unroll
            for (int r = 0; r < 4; r++) acc[i][j][r] = 0.f;

    const int ar = t >> 1;
    const int ap = (t & 1) * 4;
    const int kp = t >> 5;

    for (int kb = 0; kb < Kp; kb += 8) {
        {
            uint4 hi = *(const uint4*)(Ag + (size_t)(row0 + ar) * Kp + kb + ap);
            As[ap + 0][ar] = hi.x; As[ap + 1][ar] = hi.y;
            As[ap + 2][ar] = hi.z; As[ap + 3][ar] = hi.w;
        }
        {
            uint4 hi = *(const uint4*)(Bg + (size_t)(kb + kp) * Nc + col0 + lane * 4);
            *(uint4*)&Bs[kp][lane * 4] = hi;
        }
        __syncthreads();

        unsigned ah[2][4];
#pragma unroll
        for (int mt = 0; mt < 2; mt++) {
            int rm = wm * 32 + mt * 16 + g;
            ah[mt][0] = As[tg][rm];     ah[mt][1] = As[tg][rm + 8];
            ah[mt][2] = As[tg + 4][rm]; ah[mt][3] = As[tg + 4][rm + 8];
        }
#pragma unroll
        for (int nt = 0; nt < 8; nt++) {
            int n = wn * 64 + nt * 8 + g;
            unsigned b0 = Bs[tg][n], b1 = Bs[tg + 4][n];
#pragma unroll
            for (int mt = 0; mt < 2; mt++) mma16f(acc[mt][nt], ah[mt], b0, b1);
        }
        __syncthreads();
    }

    if (t < 128) { shS[t] = 0.f; shQ[t] = 0.f; }
    __syncthreads();

    float colS[16] = {}, colQ[16] = {};
#pragma unroll
    for (int nt = 0; nt < 8; nt++) {
        int c = col0 + wn * 64 + nt * 8 + 2 * tg;
        float2 bb = *(const float2*)&bias[c];
#pragma unroll
        for (int mt = 0; mt < 2; mt++) {
            int r = row0 + wm * 32 + mt * 16 + g;
            float v0 = acc[mt][nt][0] + bb.x, v1 = acc[mt][nt][1] + bb.y;
            float v2 = acc[mt][nt][2] + bb.x, v3 = acc[mt][nt][3] + bb.y;
            if (r < Mrows) {
                __half2 hh = __floats2half2_rn(v0, v1);
                Ch[(size_t)r * Nc2 + (c >> 1)] = *(unsigned*)&hh;
                colS[nt * 2] += v0; colQ[nt * 2] += v0 * v0;
                colS[nt * 2 + 1] += v1; colQ[nt * 2 + 1] += v1 * v1;
            }
            if (r + 8 < Mrows) {
                __half2 hh = __floats2half2_rn(v2, v3);
                Ch[(size_t)(r + 8) * Nc2 + (c >> 1)] = *(unsigned*)&hh;
                colS[nt * 2] += v2; colQ[nt * 2] += v2 * v2;
                colS[nt * 2 + 1] += v3; colQ[nt * 2 + 1] += v3 * v3;
            }
        }
    }
#pragma unroll
    for (int off = 4; off <= 16; off <<= 1)
#pragma unroll
        for (int i = 0; i < 16; i++) {
            colS[i] += __shfl_xor_sync(0xffffffffu, colS[i], off);
            colQ[i] += __shfl_xor_sync(0xffffffffu, colQ[i], off);
        }
    if (g == 0) {
#pragma unroll
        for (int i = 0; i < 16; i++) {
            int cc = wn * 64 + (i >> 1) * 8 + 2 * tg + (i & 1);
            atomicAdd(&shS[cc], colS[i]);
            atomicAdd(&shQ[cc], colQ[i]);
        }
    }
    __syncthreads();
    if (t < 128) {
        atomicAdd(&stats[col0 + t], shS[t]);
        atomicAdd(&stats[HID + col0 + t], shQ[t]);
    }
}

// ---------------- projection of h1 (bn inline) ----------------
__global__ void k_proj1(const unsigned* __restrict__ C, const float* __restrict__ stats,
                        const float* __restrict__ g, const float* __restrict__ b,
                        const float* __restrict__ HW, uint4* __restrict__ q) {
    int node = (blockIdx.x * blockDim.x + threadIdx.x) >> 5;
    int lane = threadIdx.x & 31;
    if (node >= Nn) return;
    float acc[NCLS] = {};
    const unsigned* row = C + (size_t)node * 128;
    for (int kp = lane; kp < 128; kp += 32) {
        float2 f = __half22float2(*(const __half2*)&row[kp]);
        float sc0, sh0, sc1, sh1;
        bn_inline(stats, g, b, 2 * kp, sc0, sh0);
        bn_inline(stats, g, b, 2 * kp + 1, sc1, sh1);
        f.x = fmaxf(f.x * sc0 + sh0, 0.f);
        f.y = fmaxf(f.y * sc1 + sh1, 0.f);
        const float* w = HW + (size_t)(HID + 2 * kp) * NCLS;
#pragma unroll
        for (int c = 0; c < NCLS; c++) acc[c] += f.x * w[c] + f.y * w[NCLS + c];
    }
#pragma unroll
    for (int o = 16; o > 0; o >>= 1)
#pragma unroll
        for (int c = 0; c < NCLS; c++) acc[c] += __shfl_down_sync(0xffffffffu, acc[c], o);
    if (lane == 0) {
        float f16[16];
#pragma unroll
        for (int c = 0; c < NCLS; c++) f16[c] = acc[c];
#pragma unroll
        for (int c = NCLS; c < 16; c++) f16[c] = 0.f;
        q[(size_t)node * 2] = pack8h(f16);
        q[(size_t)node * 2 + 1] = pack8h(f16 + 8);
    }
}

// ---------------- head + segment accumulate ----------------
__global__ void k_head_seg(const unsigned* __restrict__ p0, const uint4* __restrict__ qr,
                           const float* __restrict__ dinv, const int* __restrict__ batch,
                           const float* __restrict__ W, const float* __restrict__ hb,
                           float* __restrict__ ssum, float* __restrict__ scnt) {
    int node = (blockIdx.x * blockDim.x + threadIdx.x) >> 5;
    int lane = threadIdx.x & 31;
    if (node >= Nn) return;
    float acc[NCLS] = {};
    const unsigned* r0 = p0 + (size_t)node * 128;
    for (int kp = lane; kp < 128; kp += 32) {
        float2 f0 = __half22float2(*(const __half2*)&r0[kp]);
        const float* w = W + (size_t)(2 * kp) * NCLS;
#pragma unroll
        for (int c = 0; c < NCLS; c++) acc[c] += f0.x * w[c] + f0.y * w[NCLS + c];
    }
#pragma unroll
    for (int o = 16; o > 0; o >>= 1)
#pragma unroll
        for (int c = 0; c < NCLS; c++) acc[c] += __shfl_down_sync(0xffffffffu, acc[c], o);
    if (lane == 0) {
        uint4 a = __ldg(&qr[(size_t)node * 2]);
        uint4 b = __ldg(&qr[(size_t)node * 2 + 1]);
        float pool1[16];
        {
            const __half2* h = (const __half2*)&a;
#pragma unroll
            for (int qn = 0; qn < 4; qn++) {
                float2 f = __half22float2(h[qn]);
                pool1[2 * qn] = f.x;
                pool1[2 * qn + 1] = f.y;
            }
            const __half2* h2 = (const __half2*)&b;
#pragma unroll
            for (int qn = 0; qn < 4; qn++) {
                float2 f = __half22float2(h2[qn]);
                pool1[8 + 2 * qn] = f.x;
                pool1[8 + 2 * qn + 1] = f.y;
            }
        }
        float d = dinv[node];
        int bb = batch[node];
        atomicAdd(&scnt[bb], 1.f);
#pragma unroll
        for (int c = 0; c < NCLS; c++)
            atomicAdd(&ssum[bb * NCLS + c], (acc[c] + pool1[c]) * d + hb[c]);
    }
}

__global__ void k_fin(const float* __restrict__ ssum, const float* __restrict__ scnt,
                      float* __restrict__ dout) {
    int t = blockIdx.x * blockDim.x + threadIdx.x;
    if (t < NG * NCLS) {
        int gidx = t / NCLS;
        dout[t] = ssum[t] / fmaxf(scnt[gidx], 1.f);
    }
}

// ---------------- host ----------------
extern "C" void kernel_launch(void* const* d_in, const int* in_sizes, int n_in,
                              void* d_out, int out_size) {
    const float* X = (const float*)d_in[0];
    const int* node_idx = (const int*)d_in[1];
    const int* edge_idx = (const int*)d_in[2];
    const int* all_batch = (const int*)d_in[3];
    const float* W1_0 = (const float*)d_in[4];
    const float* b1_0 = (const float*)d_in[5];
    const float* g1_0 = (const float*)d_in[6];
    const float* be1_0 = (const float*)d_in[7];
    const float* W2_0 = (const float*)d_in[8];
    const float* b2_0 = (const float*)d_in[9];
    const float* bng_0 = (const float*)d_in[10];
    const float* bnb_0 = (const float*)d_in[11];
    const float* W1_1 = (const float*)d_in[12];
    const float* b1_1 = (const float*)d_in[13];
    const float* g1_1 = (const float*)d_in[14];
    const float* be1_1 = (const float*)d_in[15];
    const float* W2_1 = (const float*)d_in[16];
    const float* b2_1 = (const float*)d_in[17];
    const float* bng_1 = (const float*)d_in[18];
    const float* bnb_1 = (const float*)d_in[19];
    const float* head_W = (const float*)d_in[20];
    const float* head_b = (const float*)d_in[21];

    float *dinv, *stats, *ssum, *scnt;
    unsigned *A, *C, *hh, *P0h, *W, *q, *qe, *qr;
    __half *Xh, *Eh;
    int *ecnt, *estart, *ecur, *elist, *ncnt, *nstart, *ncur, *nlist, *blksum;
    cudaGetSymbolAddress((void**)&A, g_A);
    cudaGetSymbolAddress((void**)&C, g_C);
    cudaGetSymbolAddress((void**)&hh, g_hh);
    cudaGetSymbolAddress((void**)&P0h, g_P0h);
    cudaGetSymbolAddress((void**)&W, g_W);
    cudaGetSymbolAddress((void**)&q, g_q);
    cudaGetSymbolAddress((void**)&qe, g_qe);
    cudaGetSymbolAddress((void**)&qr, g_qr);
    cudaGetSymbolAddress((void**)&Xh, g_Xh);
    cudaGetSymbolAddress((void**)&Eh, g_Eh);
    cudaGetSymbolAddress((void**)&dinv, g_dinv);
    cudaGetSymbolAddress((void**)&stats, g_stats);
    cudaGetSymbolAddress((void**)&ssum, g_segsum);
    cudaGetSymbolAddress((void**)&scnt, g_segcnt);
    cudaGetSymbolAddress((void**)&ecnt, g_ecnt);
    cudaGetSymbolAddress((void**)&estart, g_estart);
    cudaGetSymbolAddress((void**)&ecur, g_ecur);
    cudaGetSymbolAddress((void**)&elist, g_elist);
    cudaGetSymbolAddress((void**)&ncnt, g_ncnt);
    cudaGetSymbolAddress((void**)&nstart, g_nstart);
    cudaGetSymbolAddress((void**)&ncur, g_ncur);
    cudaGetSymbolAddress((void**)&nlist, g_nlist);
    cudaGetSymbolAddress((void**)&blksum, g_blksum);

    float* stats0 = stats;
    float* stats1 = stats + 2 * HID;
    float* stats2 = stats + 4 * HID;
    float* stats3 = stats + 6 * HID;

    const int SB = 256;
    const int nnz_blocks = (NNZv + SB - 1) / SB;
    const int ge = (Mm * 32 + SB - 1) / SB;
    const int gn = (Nn * 32 + SB - 1) / SB;
    const int cvt_blocks = (Nn * HID / 8 + SB - 1) / SB;
    dim3 tc_grid(HID / 128, NPAD / 128);

    // ---- CSR build + weight packing ----
    k_init<<<64, SB>>>(ecnt, ncnt, stats, ssum, scnt);
    k_wsplit_all<<<(114688 + SB - 1) / SB, SB>>>(W1_0, W2_0, W1_1, W2_1, W);
    k_hist<<<nnz_blocks, SB>>>(node_idx, edge_idx, ecnt, ncnt);
    k_scan_blk<<<NCHUNK, 1024>>>(ecnt, ncnt, estart, nstart, blksum);
    k_scan_add<<<NCHUNK, 1024>>>(estart, nstart, ecur, ncur, blksum);
    k_fill<<<nnz_blocks, SB>>>(node_idx, edge_idx, ecur, elist, ncur, nlist);

    // ---- layer 0 ----
    k_cvtX<<<(Nn * FT / 8 + SB - 1) / SB, SB>>>(X, (uint4*)Xh);
    k_gath<128><<<ge, SB>>>((const uint4*)Xh, estart, elist, (uint4*)Eh, Mm);
    k_gath<128><<<gn, SB>>>((const uint4*)Eh, nstart, nlist, (uint4*)A, Nn);
    k_gemm_tc<<<tc_grid, 256>>>(A, W + OFF_W10, b1_0, C, stats0, FT, HID, Nn);
    k_bnrelu_cvt<<<cvt_blocks, SB>>>((const uint4*)C, stats0, g1_0, be1_0, (uint4*)A);
    k_gemm_tc<<<tc_grid, 256>>>(A, W + OFF_W20, b2_0, C, stats1, HID, HID, Nn);

    // ---- layer 1 ----
    k_bnrelu_cvt<<<cvt_blocks, SB>>>((const uint4*)C, stats1, bng_0, bnb_0, (uint4*)hh);
    k_gath<256><<<ge, SB>>>((const uint4*)hh, estart, elist, (uint4*)Eh, Mm);
    k_gath<256><<<gn, SB>>>((const uint4*)Eh, nstart, nlist, (uint4*)P0h, Nn);
    k_gemm_tc<<<tc_grid, 256>>>(P0h, W + OFF_W11, b1_1, C, stats2, HID, HID, Nn);
    k_bnrelu_cvt<<<cvt_blocks, SB>>>((const uint4*)C, stats2, g1_1, be1_1, (uint4*)A);
    k_gemm_tc<<<tc_grid, 256>>>(A, W + OFF_W21, b2_1, C, stats3, HID, HID, Nn);

    // ---- h1 branch: project, pool in 16-ch space (node pass also computes dinv) ----
    k_proj1<<<gn, SB>>>(C, stats3, bng_1, bnb_1, head_W, (uint4*)q);
    k_gath16<<<ge, SB>>>((const uint4*)q, estart, elist, (uint4*)qe, Mm);
    k_gath16_dinv<<<gn, SB>>>((const uint4*)qe, nstart, nlist, estart, (uint4*)qr, dinv);

    // ---- fused head + readout ----
    k_head_seg<<<gn, SB>>>(P0h, (const uint4*)qr, dinv, all_batch, head_W, head_b, ssum, scnt);
    k_fin<<<(NG * NCLS + SB - 1) / SB, SB>>>(ssum, scnt, (float*)d_out);
}

// round 17
// speedup vs baseline: 1.1688x; 1.1688x over previous
#include <cuda_runtime.h>
#include <cuda_fp16.h>

#define Nn 40000
#define NPAD 40064
#define Mm 10000
#define NNZv 400000
#define FT 128
#define HID 256
#define NCLS 10
#define NG 128
#define BN_EPS 1e-5f
#define NTOT (Mm + Nn)
#define NCHUNK ((NTOT + 1023) / 1024)

// ---------------- scratch (all intermediates fp16, packed in channel pairs) ----------------
__device__ unsigned g_A[(size_t)NPAD * 128];
__device__ unsigned g_C[(size_t)NPAD * 128];
__device__ unsigned g_hh[(size_t)Nn * 128];
__device__ unsigned g_P0h[(size_t)NPAD * 128];
__device__ unsigned g_W[114688];
__device__ unsigned g_q[(size_t)Nn * 8];
__device__ unsigned g_qe[(size_t)Mm * 8];
__device__ unsigned g_qr[(size_t)Nn * 8];
__device__ __half g_Xh[(size_t)Nn * FT];
__device__ __half g_Eh[(size_t)Mm * HID];
__device__ float g_dinv[Nn];
__device__ float g_stats[2 * HID];
__device__ float g_bn[2 * HID];
__device__ float g_segsum[NG * NCLS];
__device__ float g_segcnt[NG];
__device__ int g_ecnt[Mm];
__device__ int g_estart[Mm + 1];
__device__ int g_ecur[Mm];
__device__ int g_elist[NNZv];
__device__ int g_ncnt[Nn];
__device__ int g_nstart[Nn + 1];
__device__ int g_ncur[Nn];
__device__ int g_nlist[NNZv];
__device__ int g_blksum[NCHUNK];

#define OFF_W10 0
#define OFF_W20 16384
#define OFF_W11 49152
#define OFF_W21 81920

// ---------------- init ----------------
__global__ void k_init(int* ecnt, int* ncnt, float* stats, float* ssum, float* scnt) {
    int i = blockIdx.x * blockDim.x + threadIdx.x;
    int stride = gridDim.x * blockDim.x;
    for (int j = i; j < Mm; j += stride) ecnt[j] = 0;
    for (int j = i; j < Nn; j += stride) ncnt[j] = 0;
    if (i < 2 * HID) stats[i] = 0.f;
    if (i < NG * NCLS) ssum[i] = 0.f;
    if (i < NG) scnt[i] = 0.f;
}

__global__ void k_wsplit_all(const float* __restrict__ W10, const float* __restrict__ W20,
                             const float* __restrict__ W11, const float* __restrict__ W21,
                             unsigned* __restrict__ o) {
    int idx = blockIdx.x * blockDim.x + threadIdx.x;
    if (idx >= 114688) return;
    const float* W;
    int li;
    if (idx < 16384) { W = W10; li = idx; }
    else if (idx < 49152) { W = W20; li = idx - 16384; }
    else if (idx < 81920) { W = W11; li = idx - 49152; }
    else { W = W21; li = idx - 81920; }
    int kp = li / HID, c = li % HID;
    __half2 h = __floats2half2_rn(W[(size_t)(2 * kp) * HID + c],
                                  W[(size_t)(2 * kp + 1) * HID + c]);
    o[idx] = *(unsigned*)&h;
}

// ---------------- CSR build ----------------
__global__ void k_hist(const int* __restrict__ nidx, const int* __restrict__ eidx,
                       int* __restrict__ ecnt, int* __restrict__ ncnt) {
    int i = blockIdx.x * blockDim.x + threadIdx.x;
    if (i < NNZv) {
        atomicAdd(&ecnt[eidx[i]], 1);
        atomicAdd(&ncnt[nidx[i]], 1);
    }
}

__global__ void k_scan_blk(const int* __restrict__ ecnt, const int* __restrict__ ncnt,
                           int* __restrict__ estart, int* __restrict__ nstart,
                           int* __restrict__ blksum) {
    __shared__ int wsum[32];
    int t = threadIdx.x, w = t >> 5, l = t & 31;
    int gi = blockIdx.x * 1024 + t;
    int v = 0;
    if (gi < Mm) v = ecnt[gi];
    else if (gi < NTOT) v = ncnt[gi - Mm];
    int x = v;
#pragma unroll
    for (int off = 1; off < 32; off <<= 1) {
        int y = __shfl_up_sync(0xffffffffu, x, off);
        if (l >= off) x += y;
    }
    if (l == 31) wsum[w] = x;
    __syncthreads();
    if (w == 0) {
        int s = wsum[l];
#pragma unroll
        for (int off = 1; off < 32; off <<= 1) {
            int y = __shfl_up_sync(0xffffffffu, s, off);
            if (l >= off) s += y;
        }
        wsum[l] = s;
    }
    __syncthreads();
    int excl = x - v + (w ? wsum[w - 1] : 0);
    if (gi < Mm) estart[gi] = excl;
    else if (gi < NTOT) nstart[gi - Mm] = excl;
    if (t == 1023) blksum[blockIdx.x] = excl + v;
}

__global__ void k_scan_add(int* __restrict__ estart, int* __restrict__ nstart,
                           int* __restrict__ ecur, int* __restrict__ ncur,
                           const int* __restrict__ blksum) {
    __shared__ int offs;
    int t = threadIdx.x;
    if (t == 0) {
        int o = 0;
        for (int c = 0; c < (int)blockIdx.x; c++) o += blksum[c];
        offs = o;
    }
    __syncthreads();
    int gi = blockIdx.x * 1024 + t;
    if (gi < Mm) {
        int v = estart[gi] + offs;
        estart[gi] = v;
        ecur[gi] = v;
    } else if (gi < NTOT) {
        int v = nstart[gi - Mm] + offs - NNZv;
        nstart[gi - Mm] = v;
        ncur[gi - Mm] = v;
    }
    if (gi == 0) {
        estart[Mm] = NNZv;
        nstart[Nn] = NNZv;
    }
}

__global__ void k_fill(const int* __restrict__ nidx, const int* __restrict__ eidx,
                       int* __restrict__ ecur, int* __restrict__ elist,
                       int* __restrict__ ncur, int* __restrict__ nlist) {
    int i = blockIdx.x * blockDim.x + threadIdx.x;
    if (i < NNZv) {
        int e = eidx[i], n = nidx[i];
        elist[atomicAdd(&ecur[e], 1)] = n;
        nlist[atomicAdd(&ncur[n], 1)] = e;
    }
}

// ---------------- converts ----------------
__device__ __forceinline__ uint4 pack8h(const float* f) {
    uint4 u;
    __half2 h0 = __float22half2_rn(make_float2(f[0], f[1]));
    __half2 h1 = __float22half2_rn(make_float2(f[2], f[3]));
    __half2 h2 = __float22half2_rn(make_float2(f[4], f[5]));
    __half2 h3 = __float22half2_rn(make_float2(f[6], f[7]));
    u.x = *(unsigned*)&h0; u.y = *(unsigned*)&h1;
    u.z = *(unsigned*)&h2; u.w = *(unsigned*)&h3;
    return u;
}

__global__ void k_cvtX(const float* __restrict__ src, uint4* __restrict__ dst) {
    int i = blockIdx.x * blockDim.x + threadIdx.x;
    if (i >= Nn * FT / 8) return;
    float f[8];
    *(float4*)&f[0] = *(const float4*)(src + (size_t)i * 8);
    *(float4*)&f[4] = *(const float4*)(src + (size_t)i * 8 + 4);
    dst[i] = pack8h(f);
}

// fp16 in + precomputed bn -> relu fp16 out
__global__ void k_bnrelu_cvt(const uint4* __restrict__ src, const float* __restrict__ bn,
                             uint4* __restrict__ dst) {
    int i = blockIdx.x * blockDim.x + threadIdx.x;
    if (i >= Nn * HID / 8) return;
    int c8 = (i & 31) * 8;
    uint4 u = src[i];
    float f[8], sc[8], sh[8];
    const __half2* h = (const __half2*)&u;
#pragma unroll
    for (int q = 0; q < 4; q++) {
        float2 v = __half22float2(h[q]);
        f[2 * q] = v.x;
        f[2 * q + 1] = v.y;
    }
    *(float4*)&sc[0] = *(const float4*)(bn + c8);
    *(float4*)&sc[4] = *(const float4*)(bn + c8 + 4);
    *(float4*)&sh[0] = *(const float4*)(bn + HID + c8);
    *(float4*)&sh[4] = *(const float4*)(bn + HID + c8 + 4);
#pragma unroll
    for (int j = 0; j < 8; j++) f[j] = fmaxf(f[j] * sc[j] + sh[j], 0.f);
    dst[i] = pack8h(f);
}

// ---------------- fp16 CSR segment-sum gather ----------------
__device__ __forceinline__ void acc8(float* acc, uint4 v) {
    const __half2* h = (const __half2*)&v;
#pragma unroll
    for (int q = 0; q < 4; q++) {
        float2 f = __half22float2(h[q]);
        acc[2 * q] += f.x;
        acc[2 * q + 1] += f.y;
    }
}

template <int D>
__global__ void k_gath(const uint4* __restrict__ src, const int* __restrict__ start,
                       const int* __restrict__ list, uint4* __restrict__ d0, int rows) {
    int row = (blockIdx.x * blockDim.x + threadIdx.x) >> 5;
    int lane = threadIdx.x & 31;
    if (row >= rows) return;
    int s = __ldg(&start[row]), e = __ldg(&start[row + 1]);
    float acc[8] = {};
    if (D == 256) {
        for (int j0 = s; j0 < e; j0 += 32) {
            int cnt = min(32, e - j0);
            int id = (lane < cnt) ? __ldg(&list[j0 + lane]) : 0;
            int jj = 0;
            for (; jj + 4 <= cnt; jj += 4) {
                int r0 = __shfl_sync(0xffffffffu, id, jj);
                int r1 = __shfl_sync(0xffffffffu, id, jj + 1);
                int r2 = __shfl_sync(0xffffffffu, id, jj + 2);
                int r3 = __shfl_sync(0xffffffffu, id, jj + 3);
                uint4 v0 = __ldg(&src[(size_t)r0 * 32 + lane]);
                uint4 v1 = __ldg(&src[(size_t)r1 * 32 + lane]);
                uint4 v2 = __ldg(&src[(size_t)r2 * 32 + lane]);
                uint4 v3 = __ldg(&src[(size_t)r3 * 32 + lane]);
                acc8(acc, v0); acc8(acc, v1); acc8(acc, v2); acc8(acc, v3);
            }
            for (; jj < cnt; jj++) {
                int r = __shfl_sync(0xffffffffu, id, jj);
                acc8(acc, __ldg(&src[(size_t)r * 32 + lane]));
            }
        }
    } else {
        int oct = lane & 15, par = lane >> 4;
        for (int j0 = s; j0 < e; j0 += 32) {
            int cnt = min(32, e - j0);
            int id = (lane < cnt) ? __ldg(&list[j0 + lane]) : 0;
            int jj = 0;
            for (; jj + 4 <= cnt; jj += 4) {
                int q0 = __shfl_sync(0xffffffffu, id, jj);
                int q1 = __shfl_sync(0xffffffffu, id, jj + 1);
                int q2 = __shfl_sync(0xffffffffu, id, jj + 2);
                int q3 = __shfl_sync(0xffffffffu, id, jj + 3);
                int ra = par ? q1 : q0;
                int rb = par ? q3 : q2;
                uint4 va = __ldg(&src[(size_t)ra * 16 + oct]);
                uint4 vb = __ldg(&src[(size_t)rb * 16 + oct]);
                acc8(acc, va); acc8(acc, vb);
            }
            for (; jj < cnt; jj += 2) {
                int q0 = __shfl_sync(0xffffffffu, id, jj);
                int q1 = __shfl_sync(0xffffffffu, id, min(jj + 1, cnt - 1));
                int idxn = jj + par;
                int r = par ? q1 : q0;
                if (idxn < cnt)
                    acc8(acc, __ldg(&src[(size_t)r * 16 + oct]));
            }
        }
#pragma unroll
        for (int q = 0; q < 8; q++) acc[q] += __shfl_xor_sync(0xffffffffu, acc[q], 16);
        if (par) return;
        lane = oct;
    }
    d0[(size_t)row * (D / 8) + lane] = pack8h(acc);
}

// ---------------- D=16 gathers ----------------
__global__ void k_gath16(const uint4* __restrict__ src, const int* __restrict__ start,
                         const int* __restrict__ list, uint4* __restrict__ dst, int rows) {
    int row = (blockIdx.x * blockDim.x + threadIdx.x) >> 5;
    int lane = threadIdx.x & 31;
    if (row >= rows) return;
    int s = __ldg(&start[row]), e = __ldg(&start[row + 1]);
    float acc[16] = {};
    for (int j = s + lane; j < e; j += 32) {
        int r = __ldg(&list[j]);
        uint4 a = __ldg(&src[(size_t)r * 2]);
        uint4 b = __ldg(&src[(size_t)r * 2 + 1]);
        acc8(acc, a);
        acc8(acc + 8, b);
    }
#pragma unroll
    for (int off = 16; off > 0; off >>= 1)
#pragma unroll
        for (int q = 0; q < 16; q++) acc[q] += __shfl_xor_sync(0xffffffffu, acc[q], off);
    if (lane == 0) {
        dst[(size_t)row * 2] = pack8h(acc);
        dst[(size_t)row * 2 + 1] = pack8h(acc + 8);
    }
}

// node pass + fused dinv computation (walks nlist anyway)
__global__ void k_gath16_dinv(const uint4* __restrict__ src, const int* __restrict__ nstart,
                              const int* __restrict__ nlist, const int* __restrict__ estart,
                              uint4* __restrict__ dst, float* __restrict__ dinv) {
    int row = (blockIdx.x * blockDim.x + threadIdx.x) >> 5;
    int lane = threadIdx.x & 31;
    if (row >= Nn) return;
    int s = __ldg(&nstart[row]), e = __ldg(&nstart[row + 1]);
    float acc[16] = {};
    float dsum = 0.f;
    for (int j = s + lane; j < e; j += 32) {
        int r = __ldg(&nlist[j]);
        uint4 a = __ldg(&src[(size_t)r * 2]);
        uint4 b = __ldg(&src[(size_t)r * 2 + 1]);
        acc8(acc, a);
        acc8(acc + 8, b);
        dsum += (float)(__ldg(&estart[r + 1]) - __ldg(&estart[r]));
    }
#pragma unroll
    for (int off = 16; off > 0; off >>= 1) {
#pragma unroll
        for (int q = 0; q < 16; q++) acc[q] += __shfl_xor_sync(0xffffffffu, acc[q], off);
        dsum += __shfl_xor_sync(0xffffffffu, dsum, off);
    }
    if (lane == 0) {
        dst[(size_t)row * 2] = pack8h(acc);
        dst[(size_t)row * 2 + 1] = pack8h(acc + 8);
        dinv[row] = (dsum > 0.f) ? 1.f / dsum : 1.f;
    }
}

// ---------------- fp16 tensor-core GEMM: fp16 in, fp16 out, fused BN stats ----------------
__device__ __forceinline__ void mma16f(float* c, const unsigned* a, unsigned b0, unsigned b1) {
    asm volatile(
        "mma.sync.aligned.m16n8k16.row.col.f32.f16.f16.f32 "
        "{%0,%1,%2,%3}, {%4,%5,%6,%7}, {%8,%9}, {%0,%1,%2,%3};"
        : "+f"(c[0]), "+f"(c[1]), "+f"(c[2]), "+f"(c[3])
        : "r"(a[0]), "r"(a[1]), "r"(a[2]), "r"(a[3]), "r"(b0), "r"(b1));
}

__global__ __launch_bounds__(256) void k_gemm_tc(
    const unsigned* __restrict__ Ag, const unsigned* __restrict__ Bg,
    const float* __restrict__ bias, unsigned* __restrict__ Ch,
    float* __restrict__ stats, int K, int Nc, int Mrows) {
    __shared__ unsigned As[8][132];
    __shared__ unsigned Bs[8][132];
    __shared__ float shS[128], shQ[128];
    const int t = threadIdx.x;
    const int wid = t >> 5, lane = t & 31;
    const int wm = wid & 3, wn = wid >> 2;
    const int g = lane >> 2, tg = lane & 3;
    const int row0 = blockIdx.y * 128, col0 = blockIdx.x * 128;
    const int Kp = K / 2;
    const int Nc2 = Nc / 2;

    float acc[2][8][4];
#pragma unroll
    for (int i = 0; i < 2; i++)
#pragma unroll
        for (int j = 0; j < 8; j++)
#pragma unroll
            for (int r = 0; r < 4; r++) acc[i][j][r] = 0.f;

    const int ar = t >> 1;
    const int ap = (t & 1) * 4;
    const int kp = t >> 5;

    for (int kb = 0; kb < Kp; kb += 8) {
        {
            uint4 hi = *(const uint4*)(Ag + (size_t)(row0 + ar) * Kp + kb + ap);
            As[ap + 0][ar] = hi.x; As[ap + 1][ar] = hi.y;
            As[ap + 2][ar] = hi.z; As[ap + 3][ar] = hi.w;
        }
        {
            uint4 hi = *(const uint4*)(Bg + (size_t)(kb + kp) * Nc + col0 + lane * 4);
            *(uint4*)&Bs[kp][lane * 4] = hi;
        }
        __syncthreads();

        unsigned ah[2][4];
#pragma unroll
        for (int mt = 0; mt < 2; mt++) {
            int rm = wm * 32 + mt * 16 + g;
            ah[mt][0] = As[tg][rm];     ah[mt][1] = As[tg][rm + 8];
            ah[mt][2] = As[tg + 4][rm]; ah[mt][3] = As[tg + 4][rm + 8];
        }
#pragma unroll
        for (int nt = 0; nt < 8; nt++) {
            int n = wn * 64 + nt * 8 + g;
            unsigned b0 = Bs[tg][n], b1 = Bs[tg + 4][n];
#pragma unroll
            for (int mt = 0; mt < 2; mt++) mma16f(acc[mt][nt], ah[mt], b0, b1);
        }
        __syncthreads();
    }

    if (t < 128) { shS[t] = 0.f; shQ[t] = 0.f; }
    __syncthreads();

    float colS[16] = {}, colQ[16] = {};
#pragma unroll
    for (int nt = 0; nt < 8; nt++) {
        int c = col0 + wn * 64 + nt * 8 + 2 * tg;
        float2 bb = *(const float2*)&bias[c];
#pragma unroll
        for (int mt = 0; mt < 2; mt++) {
            int r = row0 + wm * 32 + mt * 16 + g;
            float v0 = acc[mt][nt][0] + bb.x, v1 = acc[mt][nt][1] + bb.y;
            float v2 = acc[mt][nt][2] + bb.x, v3 = acc[mt][nt][3] + bb.y;
            if (r < Mrows) {
                __half2 hh = __floats2half2_rn(v0, v1);
                Ch[(size_t)r * Nc2 + (c >> 1)] = *(unsigned*)&hh;
                colS[nt * 2] += v0; colQ[nt * 2] += v0 * v0;
                colS[nt * 2 + 1] += v1; colQ[nt * 2 + 1] += v1 * v1;
            }
            if (r + 8 < Mrows) {
                __half2 hh = __floats2half2_rn(v2, v3);
                Ch[(size_t)(r + 8) * Nc2 + (c >> 1)] = *(unsigned*)&hh;
                colS[nt * 2] += v2; colQ[nt * 2] += v2 * v2;
                colS[nt * 2 + 1] += v3; colQ[nt * 2 + 1] += v3 * v3;
            }
        }
    }
#pragma unroll
    for (int off = 4; off <= 16; off <<= 1)
#pragma unroll
        for (int i = 0; i < 16; i++) {
            colS[i] += __shfl_xor_sync(0xffffffffu, colS[i], off);
            colQ[i] += __shfl_xor_sync(0xffffffffu, colQ[i], off);
        }
    if (g == 0) {
#pragma unroll
        for (int i = 0; i < 16; i++) {
            int cc = wn * 64 + (i >> 1) * 8 + 2 * tg + (i & 1);
            atomicAdd(&shS[cc], colS[i]);
            atomicAdd(&shQ[cc], colQ[i]);
        }
    }
    __syncthreads();
    if (t < 128) {
        atomicAdd(&stats[col0 + t], shS[t]);
        atomicAdd(&stats[HID + col0 + t], shQ[t]);
    }
}

// ---------------- BN params (consumes + re-zeroes stats) ----------------
__global__ void k_bnparams(float* __restrict__ stats, const float* __restrict__ g,
                           const float* __restrict__ b, float* __restrict__ bn) {
    int c = threadIdx.x;
    float mean = stats[c] * (1.f / Nn);
    float var = stats[HID + c] * (1.f / Nn) - mean * mean;
    float sc = g[c] * rsqrtf(var + BN_EPS);
    bn[c] = sc;
    bn[HID + c] = b[c] - mean * sc;
    stats[c] = 0.f;
    stats[HID + c] = 0.f;
}

// ---------------- projection of h1: q = relu(bn(h1)) @ head_W[256:512] -> [N,16] fp16 ----------------
__global__ void k_proj1(const unsigned* __restrict__ C, const float* __restrict__ bn,
                        const float* __restrict__ HW, uint4* __restrict__ q) {
    int node = (blockIdx.x * blockDim.x + threadIdx.x) >> 5;
    int lane = threadIdx.x & 31;
    if (node >= Nn) return;
    float acc[NCLS] = {};
    const unsigned* row = C + (size_t)node * 128;
    for (int kp = lane; kp < 128; kp += 32) {
        float2 f = __half22float2(*(const __half2*)&row[kp]);
        float2 sc = *(const float2*)(bn + 2 * kp);
        float2 sh = *(const float2*)(bn + HID + 2 * kp);
        f.x = fmaxf(f.x * sc.x + sh.x, 0.f);
        f.y = fmaxf(f.y * sc.y + sh.y, 0.f);
        const float* w = HW + (size_t)(HID + 2 * kp) * NCLS;
#pragma unroll
        for (int c = 0; c < NCLS; c++) acc[c] += f.x * w[c] + f.y * w[NCLS + c];
    }
#pragma unroll
    for (int o = 16; o > 0; o >>= 1)
#pragma unroll
        for (int c = 0; c < NCLS; c++) acc[c] += __shfl_down_sync(0xffffffffu, acc[c], o);
    if (lane == 0) {
        float f16[16];
#pragma unroll
        for (int c = 0; c < NCLS; c++) f16[c] = acc[c];
#pragma unroll
        for (int c = NCLS; c < 16; c++) f16[c] = 0.f;
        q[(size_t)node * 2] = pack8h(f16);
        q[(size_t)node * 2 + 1] = pack8h(f16 + 8);
    }
}

// ---------------- head + segment accumulate ----------------
__global__ void k_head_seg(const unsigned* __restrict__ p0, const uint4* __restrict__ qr,
                           const float* __restrict__ dinv, const int* __restrict__ batch,
                           const float* __restrict__ W, const float* __restrict__ hb,
                           float* __restrict__ ssum, float* __restrict__ scnt) {
    int node = (blockIdx.x * blockDim.x + threadIdx.x) >> 5;
    int lane = threadIdx.x & 31;
    if (node >= Nn) return;
    float acc[NCLS] = {};
    const unsigned* r0 = p0 + (size_t)node * 128;
    for (int kp = lane; kp < 128; kp += 32) {
        float2 f0 = __half22float2(*(const __half2*)&r0[kp]);
        const float* w = W + (size_t)(2 * kp) * NCLS;
#pragma unroll
        for (int c = 0; c < NCLS; c++) acc[c] += f0.x * w[c] + f0.y * w[NCLS + c];
    }
#pragma unroll
    for (int o = 16; o > 0; o >>= 1)
#pragma unroll
        for (int c = 0; c < NCLS; c++) acc[c] += __shfl_down_sync(0xffffffffu, acc[c], o);
    if (lane == 0) {
        uint4 a = __ldg(&qr[(size_t)node * 2]);
        uint4 b = __ldg(&qr[(size_t)node * 2 + 1]);
        float pool1[16];
        {
            const __half2* h = (const __half2*)&a;
#pragma unroll
            for (int qn = 0; qn < 4; qn++) {
                float2 f = __half22float2(h[qn]);
                pool1[2 * qn] = f.x;
                pool1[2 * qn + 1] = f.y;
            }
            const __half2* h2 = (const __half2*)&b;
#pragma unroll
            for (int qn = 0; qn < 4; qn++) {
                float2 f = __half22float2(h2[qn]);
                pool1[8 + 2 * qn] = f.x;
                pool1[8 + 2 * qn + 1] = f.y;
            }
        }
        float d = dinv[node];
        int bb = batch[node];
        atomicAdd(&scnt[bb], 1.f);
#pragma unroll
        for (int c = 0; c < NCLS; c++)
            atomicAdd(&ssum[bb * NCLS + c], (acc[c] + pool1[c]) * d + hb[c]);
    }
}

__global__ void k_fin(const float* __restrict__ ssum, const float* __restrict__ scnt,
                      float* __restrict__ dout) {
    int t = blockIdx.x * blockDim.x + threadIdx.x;
    if (t < NG * NCLS) {
        int gidx = t / NCLS;
        dout[t] = ssum[t] / fmaxf(scnt[gidx], 1.f);
    }
}

// ---------------- host ----------------
extern "C" void kernel_launch(void* const* d_in, const int* in_sizes, int n_in,
                              void* d_out, int out_size) {
    const float* X = (const float*)d_in[0];
    const int* node_idx = (const int*)d_in[1];
    const int* edge_idx = (const int*)d_in[2];
    const int* all_batch = (const int*)d_in[3];
    const float* W1_0 = (const float*)d_in[4];
    const float* b1_0 = (const float*)d_in[5];
    const float* g1_0 = (const float*)d_in[6];
    const float* be1_0 = (const float*)d_in[7];
    const float* W2_0 = (const float*)d_in[8];
    const float* b2_0 = (const float*)d_in[9];
    const float* bng_0 = (const float*)d_in[10];
    const float* bnb_0 = (const float*)d_in[11];
    const float* W1_1 = (const float*)d_in[12];
    const float* b1_1 = (const float*)d_in[13];
    const float* g1_1 = (const float*)d_in[14];
    const float* be1_1 = (const float*)d_in[15];
    const float* W2_1 = (const float*)d_in[16];
    const float* b2_1 = (const float*)d_in[17];
    const float* bng_1 = (const float*)d_in[18];
    const float* bnb_1 = (const float*)d_in[19];
    const float* head_W = (const float*)d_in[20];
    const float* head_b = (const float*)d_in[21];

    float *dinv, *stats, *bn, *ssum, *scnt;
    unsigned *A, *C, *hh, *P0h, *W, *q, *qe, *qr;
    __half *Xh, *Eh;
    int *ecnt, *estart, *ecur, *elist, *ncnt, *nstart, *ncur, *nlist, *blksum;
    cudaGetSymbolAddress((void**)&A, g_A);
    cudaGetSymbolAddress((void**)&C, g_C);
    cudaGetSymbolAddress((void**)&hh, g_hh);
    cudaGetSymbolAddress((void**)&P0h, g_P0h);
    cudaGetSymbolAddress((void**)&W, g_W);
    cudaGetSymbolAddress((void**)&q, g_q);
    cudaGetSymbolAddress((void**)&qe, g_qe);
    cudaGetSymbolAddress((void**)&qr, g_qr);
    cudaGetSymbolAddress((void**)&Xh, g_Xh);
    cudaGetSymbolAddress((void**)&Eh, g_Eh);
    cudaGetSymbolAddress((void**)&dinv, g_dinv);
    cudaGetSymbolAddress((void**)&stats, g_stats);
    cudaGetSymbolAddress((void**)&bn, g_bn);
    cudaGetSymbolAddress((void**)&ssum, g_segsum);
    cudaGetSymbolAddress((void**)&scnt, g_segcnt);
    cudaGetSymbolAddress((void**)&ecnt, g_ecnt);
    cudaGetSymbolAddress((void**)&estart, g_estart);
    cudaGetSymbolAddress((void**)&ecur, g_ecur);
    cudaGetSymbolAddress((void**)&elist, g_elist);
    cudaGetSymbolAddress((void**)&ncnt, g_ncnt);
    cudaGetSymbolAddress((void**)&nstart, g_nstart);
    cudaGetSymbolAddress((void**)&ncur, g_ncur);
    cudaGetSymbolAddress((void**)&nlist, g_nlist);
    cudaGetSymbolAddress((void**)&blksum, g_blksum);

    const int SB = 256;
    const int nnz_blocks = (NNZv + SB - 1) / SB;
    const int ge = (Mm * 32 + SB - 1) / SB;
    const int gn = (Nn * 32 + SB - 1) / SB;
    const int cvt_blocks = (Nn * HID / 8 + SB - 1) / SB;
    dim3 tc_grid(HID / 128, NPAD / 128);

    // ---- CSR build + weight packing ----
    k_init<<<64, SB>>>(ecnt, ncnt, stats, ssum, scnt);
    k_wsplit_all<<<(114688 + SB - 1) / SB, SB>>>(W1_0, W2_0, W1_1, W2_1, W);
    k_hist<<<nnz_blocks, SB>>>(node_idx, edge_idx, ecnt, ncnt);
    k_scan_blk<<<NCHUNK, 1024>>>(ecnt, ncnt, estart, nstart, blksum);
    k_scan_add<<<NCHUNK, 1024>>>(estart, nstart, ecur, ncur, blksum);
    k_fill<<<nnz_blocks, SB>>>(node_idx, edge_idx, ecur, elist, ncur, nlist);

    // ---- layer 0 ----
    k_cvtX<<<(Nn * FT / 8 + SB - 1) / SB, SB>>>(X, (uint4*)Xh);
    k_gath<128><<<ge, SB>>>((const uint4*)Xh, estart, elist, (uint4*)Eh, Mm);
    k_gath<128><<<gn, SB>>>((const uint4*)Eh, nstart, nlist, (uint4*)A, Nn);
    k_gemm_tc<<<tc_grid, 256>>>(A, W + OFF_W10, b1_0, C, stats, FT, HID, Nn);
    k_bnparams<<<1, HID>>>(stats, g1_0, be1_0, bn);
    k_bnrelu_cvt<<<cvt_blocks, SB>>>((const uint4*)C, bn, (uint4*)A);
    k_gemm_tc<<<tc_grid, 256>>>(A, W + OFF_W20, b2_0, C, stats, HID, HID, Nn);
    k_bnparams<<<1, HID>>>(stats, bng_0, bnb_0, bn);

    // ---- layer 1 ----
    k_bnrelu_cvt<<<cvt_blocks, SB>>>((const uint4*)C, bn, (uint4*)hh);
    k_gath<256><<<ge, SB>>>((const uint4*)hh, estart, elist, (uint4*)Eh, Mm);
    k_gath<256><<<gn, SB>>>((const uint4*)Eh, nstart, nlist, (uint4*)P0h, Nn);
    k_gemm_tc<<<tc_grid, 256>>>(P0h, W + OFF_W11, b1_1, C, stats, HID, HID, Nn);
    k_bnparams<<<1, HID>>>(stats, g1_1, be1_1, bn);
    k_bnrelu_cvt<<<cvt_blocks, SB>>>((const uint4*)C, bn, (uint4*)A);
    k_gemm_tc<<<tc_grid, 256>>>(A, W + OFF_W21, b2_1, C, stats, HID, HID, Nn);
    k_bnparams<<<1, HID>>>(stats, bng_1, bnb_1, bn);

    // ---- h1 branch: project, pool in 16-ch space (node pass computes dinv) ----
    k_proj1<<<gn, SB>>>(C, bn, head_W, (uint4*)q);
    k_gath16<<<ge, SB>>>((const uint4*)q, estart, elist, (uint4*)qe, Mm);
    k_gath16_dinv<<<gn, SB>>>((const uint4*)qe, nstart, nlist, estart, (uint4*)qr, dinv);

    // ---- fused head + readout ----
    k_head_seg<<<gn, SB>>>(P0h, (const uint4*)qr, dinv, all_batch, head_W, head_b, ssum, scnt);
    k_fin<<<(NG * NCLS + SB - 1) / SB, SB>>>(ssum, scnt, (float*)d_out);
}